// round 16
// baseline (speedup 1.0000x reference)
#include <cuda_runtime.h>
#include <cstdint>

// Problem constants: B=128, C=3, H=W=256, PROB=0.9, BRI=CON=SAT=0.2, CUT=0.25 -> CH=CW=64.
#define PROB_ 0.9f
static constexpr int B_     = 128;
static constexpr int H_     = 256;
static constexpr int W_     = 256;
static constexpr int CH_    = 64;
static constexpr int CW_    = 64;
static constexpr int PLANE  = H_ * W_;        // 65536 floats
static constexpr int PLANE4 = PLANE / 4;      // 16384 float4
static constexpr int GRP    = 4;              // CTAs per batch (NO cluster)
static constexpr int NT     = 1024;           // threads per CTA
static constexpr int Q4     = PLANE4 / GRP;   // 4096 float4 per channel slice (64 rows)
static constexpr int ITQ    = Q4 / NT;        // 4 float4 per thread per channel
static constexpr int SMEM_BYTES = 3 * Q4 * 16 + 128;  // 3 channel tiles + aux

// GMEM mailbox for the per-batch mean exchange. Zero-initialized at module
// load; the g_done reset protocol restores all-zeros before kernel exit, so
// every graph replay starts from the same state (no init kernel needed).
__device__ float    g_part[B_ * 12];   // [batch][rank][ch]
__device__ unsigned g_cnt [B_];        // producers arrived
__device__ unsigned g_done[B_];        // consumers finished

// ---------------------------------------------------------------------------
// 4 plain CTAs = one batch (adjacent blockIdx) -- NO cluster, so all 148 SMs
// are usable (cluster-4 placement strands 16 SMs: CTAS_ACTIVE 132 vs 148,
// a 4.3us pure scheduling tax on this kernel). Each CTA owns 64 rows x 3
// channels (192KB) in SMEM, read from DRAM exactly once via 3 staged cp.async
// groups with the per-channel reduction overlapping in-flight loads.
//
// Mean exchange via GMEM mailbox: publish partials -> threadfence ->
// atomicAdd(g_cnt); tid0 spins until 4 (deadlock-free: peer CTAs are adjacent
// block ids, dispatch is in-order, so at most the single frontier batch can
// have undispatched members -> at most 3 CTAs spin while 145 progress).
// Last consumer (g_done==4) resets both counters to zero for the next replay.
//
// Algebra: out_ch = A*x0_ch + D*g0 + E_ch with
//   A = s*b*c ; D = (1-s)*b*c ; g0 = mean_ch(x0 pixel)
//   E_ch = (1-c)*(s*M_ch + (1-s)*Mbar),  M_ch = b*mean(raw plane ch)
// flip preserves plane means; cutout and apply are selects.
// ---------------------------------------------------------------------------
__global__ void __launch_bounds__(NT, 1)
aug_kernel(const float* __restrict__ img,
           const float* __restrict__ apply_u,
           const float* __restrict__ flip_u,
           const float* __restrict__ bri_u,
           const float* __restrict__ con_u,
           const float* __restrict__ sat_u,
           const int*   __restrict__ top_idx,
           const int*   __restrict__ left_idx,
           float* __restrict__ out)
{
    extern __shared__ float4 smem4[];                   // 3 * Q4 float4 tiles
    float* aux = reinterpret_cast<float*>(smem4 + 3 * Q4);
    // aux[8..19] = gathered partials: aux[8 + r*3 + ch]

    const int tid  = threadIdx.x;
    const int b    = blockIdx.x >> 2;
    const int rank = blockIdx.x & 3;

    // Slice base (float4 units): batch base + rank's 64-row band of channel 0.
    const size_t base4 = (size_t)b * 3 * PLANE4 + (size_t)rank * Q4;
    const float4* in0 = reinterpret_cast<const float4*>(img) + base4;
    const float4* in1 = in0 + PLANE4;
    const float4* in2 = in0 + 2 * PLANE4;
    float4* out0 = reinterpret_cast<float4*>(out) + base4;
    float4* out1 = out0 + PLANE4;
    float4* out2 = out0 + 2 * PLANE4;

    const bool apply = (__ldg(apply_u + b) < PROB_);
    if (!apply) {
        // All 4 CTAs of this batch take this path; they touch no mailbox.
#pragma unroll
        for (int i = 0; i < ITQ; i++) {
            const int j = tid + i * NT;
            out0[j] = __ldg(in0 + j);
            out1[j] = __ldg(in1 + j);
            out2[j] = __ldg(in2 + j);
        }
        return;
    }

    // ---------------- Phase 1: staged GMEM -> SMEM + overlapped sums -------
    const uint32_t sbase = (uint32_t)__cvta_generic_to_shared(smem4);
#pragma unroll
    for (int ch = 0; ch < 3; ch++) {
        const float4* src = (ch == 0) ? in0 : (ch == 1) ? in1 : in2;
#pragma unroll
        for (int i = 0; i < ITQ; i++) {
            const int j = tid + i * NT;
            const uint32_t dst = sbase + (uint32_t)(ch * Q4 + j) * 16u;
            asm volatile("cp.async.cg.shared.global [%0], [%1], 16;\n"
                         :: "r"(dst), "l"(src + j));
        }
        asm volatile("cp.async.commit_group;\n");
    }

    // Sum channel k while channels k+1.. are still loading.
    float s0, s1, s2;
    {
        auto sum_ch = [&](int ch) -> float {
            float s = 0.0f;
#pragma unroll
            for (int i = 0; i < ITQ; i++) {
                const int j = tid + i * NT;
                float4 v = smem4[ch * Q4 + j];
                s += (v.x + v.y) + (v.z + v.w);
            }
            return s;
        };
        asm volatile("cp.async.wait_group 2;\n" ::: "memory");
        s0 = sum_ch(0);
        asm volatile("cp.async.wait_group 1;\n" ::: "memory");
        s1 = sum_ch(1);
        asm volatile("cp.async.wait_group 0;\n" ::: "memory");
        s2 = sum_ch(2);
    }

#pragma unroll
    for (int o = 16; o > 0; o >>= 1) {
        s0 += __shfl_xor_sync(0xFFFFFFFFu, s0, o);
        s1 += __shfl_xor_sync(0xFFFFFFFFu, s1, o);
        s2 += __shfl_xor_sync(0xFFFFFFFFu, s2, o);
    }
    __shared__ float smA[32], smB[32], smC[32];
    const int wid = tid >> 5;
    if ((tid & 31) == 0) { smA[wid] = s0; smB[wid] = s1; smC[wid] = s2; }
    __syncthreads();   // also publishes all SMEM tiles for the flip reads

    // ---------------- Publish partials + spin for siblings (GMEM mailbox) --
    if (tid < 32) {
        float a = smA[tid], d = smB[tid], e = smC[tid];
#pragma unroll
        for (int o = 16; o > 0; o >>= 1) {
            a += __shfl_xor_sync(0xFFFFFFFFu, a, o);
            d += __shfl_xor_sync(0xFFFFFFFFu, d, o);
            e += __shfl_xor_sync(0xFFFFFFFFu, e, o);
        }
        if (tid == 0) {
            const int pb = b * 12 + rank * 3;
            g_part[pb + 0] = a;
            g_part[pb + 1] = d;
            g_part[pb + 2] = e;
            __threadfence();
            atomicAdd(&g_cnt[b], 1u);
            // Spin until all 4 producers arrived. Siblings are co-resident
            // (adjacent block ids) except at most one frontier batch per
            // wave boundary, so this wait is normally ~0.
            volatile unsigned* cnt = &g_cnt[b];
            while (*cnt < 4u) __nanosleep(64);
        }
    }
    __syncthreads();

    // Gather the 12 partials in parallel into SMEM.
    if (tid < 12) aux[8 + tid] = __ldcg(&g_part[b * 12 + tid]);
    __syncthreads();

    // Reset protocol: last consumer restores counters to zero so the next
    // graph replay starts from module-load state.
    if (tid == 0) {
        __threadfence();
        unsigned old = atomicAdd(&g_done[b], 1u);
        if (old == 3u) {
            g_cnt[b] = 0u;
            __threadfence();
            g_done[b] = 0u;
        }
    }

    // ---------------- Per-batch constants -----------------------------------
    const float bv = 0.8f + 0.4f * __ldg(bri_u + b);
    const float cv = 0.8f + 0.4f * __ldg(con_u + b);
    const float sv = 0.8f + 0.4f * __ldg(sat_u + b);

    const float inv = 1.0f / (float)PLANE;
    const float M0 = (aux[8]  + aux[11] + aux[14] + aux[17]) * inv * bv;
    const float M1 = (aux[9]  + aux[12] + aux[15] + aux[18]) * inv * bv;
    const float M2 = (aux[10] + aux[13] + aux[16] + aux[19]) * inv * bv;
    const float Mbar = (M0 + M1 + M2) * (1.0f / 3.0f);

    const float A  = sv * bv * cv;
    const float D  = (1.0f - sv) * bv * cv;
    const float k  = 1.0f - cv;
    const float os = 1.0f - sv;
    const float E0 = k * (sv * M0 + os * Mbar);
    const float E1 = k * (sv * M1 + os * Mbar);
    const float E2 = k * (sv * M2 + os * Mbar);

    const bool flip = (__ldg(flip_u + b) < 0.5f);
    const int  t_   = __ldg(top_idx + b);
    const int  l_   = __ldg(left_idx + b);

    // ---------------- Phase 2: transform from SMEM, stream to DRAM ---------
#pragma unroll
    for (int i = 0; i < ITQ; i++) {
        const int j  = tid + i * NT;        // float4 idx within 64x64-f4 slice
        const int rr = j >> 6;              // local row 0..63
        const int wg = j & 63;              // output float4 column group
        const int h  = rank * 64 + rr;      // global row
        const int sj = flip ? ((rr << 6) | (63 - wg)) : j;

        float4 r = smem4[sj];
        float4 g = smem4[Q4 + sj];
        float4 c = smem4[2 * Q4 + sj];
        if (flip) {
            float t;
            t = r.x; r.x = r.w; r.w = t;  t = r.y; r.y = r.z; r.z = t;
            t = g.x; g.x = g.w; g.w = t;  t = g.y; g.y = g.z; g.z = t;
            t = c.x; c.x = c.w; c.w = t;  t = c.y; c.y = c.z; c.z = t;
        }

        const bool row_in = (h >= t_) && (h < t_ + CH_);
        const int  w0 = wg << 2;

        float4 oR, oG, oB;
        float gray; bool cut; int col;

        col = w0 + 0; cut = row_in && (col >= l_) && (col < l_ + CW_);
        gray = (r.x + g.x + c.x) * (1.0f / 3.0f);
        oR.x = cut ? 0.0f : fmaf(A, r.x, fmaf(D, gray, E0));
        oG.x = cut ? 0.0f : fmaf(A, g.x, fmaf(D, gray, E1));
        oB.x = cut ? 0.0f : fmaf(A, c.x, fmaf(D, gray, E2));

        col = w0 + 1; cut = row_in && (col >= l_) && (col < l_ + CW_);
        gray = (r.y + g.y + c.y) * (1.0f / 3.0f);
        oR.y = cut ? 0.0f : fmaf(A, r.y, fmaf(D, gray, E0));
        oG.y = cut ? 0.0f : fmaf(A, g.y, fmaf(D, gray, E1));
        oB.y = cut ? 0.0f : fmaf(A, c.y, fmaf(D, gray, E2));

        col = w0 + 2; cut = row_in && (col >= l_) && (col < l_ + CW_);
        gray = (r.z + g.z + c.z) * (1.0f / 3.0f);
        oR.z = cut ? 0.0f : fmaf(A, r.z, fmaf(D, gray, E0));
        oG.z = cut ? 0.0f : fmaf(A, g.z, fmaf(D, gray, E1));
        oB.z = cut ? 0.0f : fmaf(A, c.z, fmaf(D, gray, E2));

        col = w0 + 3; cut = row_in && (col >= l_) && (col < l_ + CW_);
        gray = (r.w + g.w + c.w) * (1.0f / 3.0f);
        oR.w = cut ? 0.0f : fmaf(A, r.w, fmaf(D, gray, E0));
        oG.w = cut ? 0.0f : fmaf(A, g.w, fmaf(D, gray, E1));
        oB.w = cut ? 0.0f : fmaf(A, c.w, fmaf(D, gray, E2));

        out0[j] = oR;
        out1[j] = oG;
        out2[j] = oB;
    }
}

extern "C" void kernel_launch(void* const* d_in, const int* in_sizes, int n_in,
                              void* d_out, int out_size) {
    const float* images       = (const float*)d_in[0];
    const float* apply_u      = (const float*)d_in[1];
    const float* flip_u       = (const float*)d_in[2];
    const float* brightness_u = (const float*)d_in[3];
    const float* contrast_u   = (const float*)d_in[4];
    const float* saturation_u = (const float*)d_in[5];
    const int*   top_idx      = (const int*)d_in[6];
    const int*   left_idx     = (const int*)d_in[7];
    float* out = (float*)d_out;

    cudaFuncSetAttribute(aug_kernel,
                         cudaFuncAttributeMaxDynamicSharedMemorySize,
                         SMEM_BYTES);

    aug_kernel<<<B_ * GRP, NT, SMEM_BYTES>>>(
        images, apply_u, flip_u, brightness_u, contrast_u, saturation_u,
        top_idx, left_idx, out);
}

// round 17
// speedup vs baseline: 1.0061x; 1.0061x over previous
#include <cuda_runtime.h>
#include <cstdint>

// Problem constants: B=128, C=3, H=W=256, PROB=0.9, BRI=CON=SAT=0.2, CUT=0.25 -> CH=CW=64.
#define PROB_ 0.9f
static constexpr int B_     = 128;
static constexpr int H_     = 256;
static constexpr int W_     = 256;
static constexpr int CH_    = 64;
static constexpr int CW_    = 64;
static constexpr int PLANE  = H_ * W_;        // 65536 floats
static constexpr int PLANE4 = PLANE / 4;      // 16384 float4
static constexpr int CLUS   = 4;              // CTAs per batch (cluster)
static constexpr int NT     = 1024;           // threads per CTA
static constexpr int Q4     = PLANE4 / CLUS;  // 4096 float4 per channel slice (64 rows)
static constexpr int ITQ    = Q4 / NT;        // 4 float4 per thread per channel
static constexpr int SMEM_BYTES = 3 * Q4 * 16 + 128;  // 3 channel tiles + aux

// ---------------------------------------------------------------------------
// One 4-CTA cluster = one batch; each CTA owns 64 rows x 3 channels (192KB) in
// SMEM, read from DRAM exactly once (3 staged cp.async groups; per-channel
// reduction overlaps in-flight loads).
//
// Mean exchange is PUSH-based: each CTA writes its 3 partials into every
// sibling's aux[8 + myrank*3 + ch] via st.shared::cluster and arrives
// (release) on the sibling's mbarrier. The consumer waits on its LOCAL
// mbarrier (4 arrivals, acquire): the arrival carries the data dependency, so
// the generic cluster barrier before the gather AND the trailing cluster
// barrier (which in R15 protected sibling READS of our SMEM) both disappear.
// The one remaining cluster arrive/wait (mbarrier-init safety) is split so
// its ~490-cycle wait overlaps all of phase 1.
//
// Algebra: out_ch = A*x0_ch + D*g0 + E_ch with
//   A = s*b*c ; D = (1-s)*b*c ; g0 = mean_ch(x0 pixel)
//   E_ch = (1-c)*(s*M_ch + (1-s)*Mbar),  M_ch = b*mean(raw plane ch)
// flip preserves plane means; cutout and apply are selects.
// ---------------------------------------------------------------------------
__global__ void __cluster_dims__(CLUS, 1, 1) __launch_bounds__(NT, 1)
aug_kernel(const float* __restrict__ img,
           const float* __restrict__ apply_u,
           const float* __restrict__ flip_u,
           const float* __restrict__ bri_u,
           const float* __restrict__ con_u,
           const float* __restrict__ sat_u,
           const int*   __restrict__ top_idx,
           const int*   __restrict__ left_idx,
           float* __restrict__ out)
{
    extern __shared__ float4 smem4[];                   // 3 * Q4 float4 tiles
    float* aux = reinterpret_cast<float*>(smem4 + 3 * Q4);
    // aux[0..2]  = this CTA's own partials (local staging)
    // aux[8..19] = pushed partials: aux[8 + r*3 + ch] from rank r
    // aux[24..25]= mbarrier (8 bytes, 8-aligned)

    const int tid  = threadIdx.x;
    const int b    = blockIdx.x >> 2;
    const int rank = blockIdx.x & 3;

    const size_t base4 = (size_t)b * 3 * PLANE4 + (size_t)rank * Q4;
    const float4* in0 = reinterpret_cast<const float4*>(img) + base4;
    const float4* in1 = in0 + PLANE4;
    const float4* in2 = in0 + 2 * PLANE4;
    float4* out0 = reinterpret_cast<float4*>(out) + base4;
    float4* out1 = out0 + PLANE4;
    float4* out2 = out0 + 2 * PLANE4;

    const bool apply = (__ldg(apply_u + b) < PROB_);
    if (!apply) {
        // Whole cluster takes this path (same batch) -> no barrier mismatch
        // (no CTA in this cluster executes any cluster/mbarrier op).
#pragma unroll
        for (int i = 0; i < ITQ; i++) {
            const int j = tid + i * NT;
            out0[j] = __ldg(in0 + j);
            out1[j] = __ldg(in1 + j);
            out2[j] = __ldg(in2 + j);
        }
        return;
    }

    const uint32_t mbar = (uint32_t)__cvta_generic_to_shared(&aux[24]);

    // mbarrier init (4 arrivals: one push from each cluster CTA incl. self),
    // then split cluster barrier: arrive now, wait just before the pushes.
    if (tid == 0) {
        asm volatile("mbarrier.init.shared.b64 [%0], 4;" :: "r"(mbar) : "memory");
    }
    __syncthreads();
    asm volatile("barrier.cluster.arrive.aligned;" ::: "memory");

    // ---------------- Phase 1: staged GMEM -> SMEM + overlapped sums -------
    const uint32_t sbase = (uint32_t)__cvta_generic_to_shared(smem4);
#pragma unroll
    for (int ch = 0; ch < 3; ch++) {
        const float4* src = (ch == 0) ? in0 : (ch == 1) ? in1 : in2;
#pragma unroll
        for (int i = 0; i < ITQ; i++) {
            const int j = tid + i * NT;
            const uint32_t dst = sbase + (uint32_t)(ch * Q4 + j) * 16u;
            asm volatile("cp.async.cg.shared.global [%0], [%1], 16;\n"
                         :: "r"(dst), "l"(src + j));
        }
        asm volatile("cp.async.commit_group;\n");
    }

    float s0, s1, s2;
    {
        auto sum_ch = [&](int ch) -> float {
            float s = 0.0f;
#pragma unroll
            for (int i = 0; i < ITQ; i++) {
                const int j = tid + i * NT;
                float4 v = smem4[ch * Q4 + j];
                s += (v.x + v.y) + (v.z + v.w);
            }
            return s;
        };
        asm volatile("cp.async.wait_group 2;\n" ::: "memory");
        s0 = sum_ch(0);
        asm volatile("cp.async.wait_group 1;\n" ::: "memory");
        s1 = sum_ch(1);
        asm volatile("cp.async.wait_group 0;\n" ::: "memory");
        s2 = sum_ch(2);
    }

#pragma unroll
    for (int o = 16; o > 0; o >>= 1) {
        s0 += __shfl_xor_sync(0xFFFFFFFFu, s0, o);
        s1 += __shfl_xor_sync(0xFFFFFFFFu, s1, o);
        s2 += __shfl_xor_sync(0xFFFFFFFFu, s2, o);
    }
    __shared__ float smA[32], smB[32], smC[32];
    const int wid = tid >> 5;
    if ((tid & 31) == 0) { smA[wid] = s0; smB[wid] = s1; smC[wid] = s2; }

    // Preload per-batch scalars: latency hides under the exchange.
    const float bv = 0.8f + 0.4f * __ldg(bri_u + b);
    const float cv = 0.8f + 0.4f * __ldg(con_u + b);
    const float sv = 0.8f + 0.4f * __ldg(sat_u + b);
    const bool flip = (__ldg(flip_u + b) < 0.5f);
    const int  t_   = __ldg(top_idx + b);
    const int  l_   = __ldg(left_idx + b);

    __syncthreads();   // publishes smA/B/C and all SMEM tiles (flip reads)
    if (tid < 32) {
        float a = smA[tid], d = smB[tid], e = smC[tid];
#pragma unroll
        for (int o = 16; o > 0; o >>= 1) {
            a += __shfl_xor_sync(0xFFFFFFFFu, a, o);
            d += __shfl_xor_sync(0xFFFFFFFFu, d, o);
            e += __shfl_xor_sync(0xFFFFFFFFu, e, o);
        }
        if (tid == 0) { aux[0] = a; aux[1] = d; aux[2] = e; }
    }
    __syncthreads();

    // ---------------- Push-based exchange ----------------------------------
    // Init-safety: all siblings' mbarriers are initialized once the split
    // cluster wait completes (arrivals happened before phase 1).
    asm volatile("barrier.cluster.wait.aligned;" ::: "memory");

    if (tid < 4) {
        // Push MY partials (aux[0..2]) into target rank `tid`'s slot for my
        // rank, then arrive (release) on the target's mbarrier.
        const float a0 = aux[0], a1 = aux[1], a2 = aux[2];
        uint32_t la = (uint32_t)__cvta_generic_to_shared(&aux[8 + rank * 3]);
        uint32_t ra;
        asm volatile("mapa.shared::cluster.u32 %0, %1, %2;"
                     : "=r"(ra) : "r"(la), "r"(tid));
        asm volatile("st.shared::cluster.f32 [%0], %1;"      :: "r"(ra),      "f"(a0) : "memory");
        asm volatile("st.shared::cluster.f32 [%0+4], %1;"    :: "r"(ra),      "f"(a1) : "memory");
        asm volatile("st.shared::cluster.f32 [%0+8], %1;"    :: "r"(ra),      "f"(a2) : "memory");
        uint32_t mra;
        asm volatile("mapa.shared::cluster.u32 %0, %1, %2;"
                     : "=r"(mra) : "r"(mbar), "r"(tid));
        asm volatile("mbarrier.arrive.release.cluster.shared::cluster.b64 _, [%0];"
                     :: "r"(mra) : "memory");
    }

    // Wait for 4 arrivals on the LOCAL mbarrier (acquire at cluster scope
    // orders the siblings' st.shared::cluster writes before our reads).
    if (tid == 0) {
        uint32_t done;
        asm volatile(
            "{\n\t"
            ".reg .pred p;\n\t"
            "mbarrier.try_wait.parity.acquire.cluster.shared::cta.b64 p, [%1], 0;\n\t"
            "selp.b32 %0, 1, 0, p;\n\t"
            "}" : "=r"(done) : "r"(mbar) : "memory");
        if (!done) {
            asm volatile(
                "{\n\t"
                ".reg .pred P1;\n\t"
                "WAIT_LOOP_%=:\n\t"
                "mbarrier.try_wait.parity.acquire.cluster.shared::cta.b64 P1, [%0], 0, 0x989680;\n\t"
                "@P1 bra.uni WAIT_DONE_%=;\n\t"
                "bra.uni WAIT_LOOP_%=;\n\t"
                "WAIT_DONE_%=:\n\t"
                "}" :: "r"(mbar) : "memory");
        }
    }
    __syncthreads();   // publish pushed partials to all threads

    // ---------------- Per-batch constants -----------------------------------
    const float inv = 1.0f / (float)PLANE;
    const float M0 = (aux[8]  + aux[11] + aux[14] + aux[17]) * inv * bv;
    const float M1 = (aux[9]  + aux[12] + aux[15] + aux[18]) * inv * bv;
    const float M2 = (aux[10] + aux[13] + aux[16] + aux[19]) * inv * bv;
    const float Mbar = (M0 + M1 + M2) * (1.0f / 3.0f);

    const float A  = sv * bv * cv;
    const float D  = (1.0f - sv) * bv * cv;
    const float k  = 1.0f - cv;
    const float os = 1.0f - sv;
    const float E0 = k * (sv * M0 + os * Mbar);
    const float E1 = k * (sv * M1 + os * Mbar);
    const float E2 = k * (sv * M2 + os * Mbar);

    // ---------------- Phase 2: transform from SMEM, stream to DRAM ---------
    // No trailing cluster barrier needed: all sibling writes into our SMEM
    // happened before their (observed) mbarrier arrivals; nobody reads ours.
#pragma unroll
    for (int i = 0; i < ITQ; i++) {
        const int j  = tid + i * NT;        // float4 idx within 64x64-f4 slice
        const int rr = j >> 6;              // local row 0..63
        const int wg = j & 63;              // output float4 column group
        const int h  = rank * 64 + rr;      // global row
        const int sj = flip ? ((rr << 6) | (63 - wg)) : j;

        float4 r = smem4[sj];
        float4 g = smem4[Q4 + sj];
        float4 c = smem4[2 * Q4 + sj];
        if (flip) {
            float t;
            t = r.x; r.x = r.w; r.w = t;  t = r.y; r.y = r.z; r.z = t;
            t = g.x; g.x = g.w; g.w = t;  t = g.y; g.y = g.z; g.z = t;
            t = c.x; c.x = c.w; c.w = t;  t = c.y; c.y = c.z; c.z = t;
        }

        const bool row_in = (h >= t_) && (h < t_ + CH_);
        const int  w0 = wg << 2;

        float4 oR, oG, oB;
        float gray; bool cut; int col;

        col = w0 + 0; cut = row_in && (col >= l_) && (col < l_ + CW_);
        gray = (r.x + g.x + c.x) * (1.0f / 3.0f);
        oR.x = cut ? 0.0f : fmaf(A, r.x, fmaf(D, gray, E0));
        oG.x = cut ? 0.0f : fmaf(A, g.x, fmaf(D, gray, E1));
        oB.x = cut ? 0.0f : fmaf(A, c.x, fmaf(D, gray, E2));

        col = w0 + 1; cut = row_in && (col >= l_) && (col < l_ + CW_);
        gray = (r.y + g.y + c.y) * (1.0f / 3.0f);
        oR.y = cut ? 0.0f : fmaf(A, r.y, fmaf(D, gray, E0));
        oG.y = cut ? 0.0f : fmaf(A, g.y, fmaf(D, gray, E1));
        oB.y = cut ? 0.0f : fmaf(A, c.y, fmaf(D, gray, E2));

        col = w0 + 2; cut = row_in && (col >= l_) && (col < l_ + CW_);
        gray = (r.z + g.z + c.z) * (1.0f / 3.0f);
        oR.z = cut ? 0.0f : fmaf(A, r.z, fmaf(D, gray, E0));
        oG.z = cut ? 0.0f : fmaf(A, g.z, fmaf(D, gray, E1));
        oB.z = cut ? 0.0f : fmaf(A, c.z, fmaf(D, gray, E2));

        col = w0 + 3; cut = row_in && (col >= l_) && (col < l_ + CW_);
        gray = (r.w + g.w + c.w) * (1.0f / 3.0f);
        oR.w = cut ? 0.0f : fmaf(A, r.w, fmaf(D, gray, E0));
        oG.w = cut ? 0.0f : fmaf(A, g.w, fmaf(D, gray, E1));
        oB.w = cut ? 0.0f : fmaf(A, c.w, fmaf(D, gray, E2));

        out0[j] = oR;
        out1[j] = oG;
        out2[j] = oB;
    }
}

extern "C" void kernel_launch(void* const* d_in, const int* in_sizes, int n_in,
                              void* d_out, int out_size) {
    const float* images       = (const float*)d_in[0];
    const float* apply_u      = (const float*)d_in[1];
    const float* flip_u       = (const float*)d_in[2];
    const float* brightness_u = (const float*)d_in[3];
    const float* contrast_u   = (const float*)d_in[4];
    const float* saturation_u = (const float*)d_in[5];
    const int*   top_idx      = (const int*)d_in[6];
    const int*   left_idx     = (const int*)d_in[7];
    float* out = (float*)d_out;

    cudaFuncSetAttribute(aug_kernel,
                         cudaFuncAttributeMaxDynamicSharedMemorySize,
                         SMEM_BYTES);

    aug_kernel<<<B_ * CLUS, NT, SMEM_BYTES>>>(
        images, apply_u, flip_u, brightness_u, contrast_u, saturation_u,
        top_idx, left_idx, out);
}